// round 1
// baseline (speedup 1.0000x reference)
#include <cuda_runtime.h>
#include <cstdint>

// Problem constants (from reference): logits [16, 2048, 1] fp32, seq_len [16] i32,
// out [16, 2048, 2048] fp32.
#define BB 16
#define TT 2048
#define RPB 8          // rows per block
#define THREADS 256

// scratch: sigmoid(logits), 16*2048 floats = 128 KB (lives in L2)
__device__ float g_scores[BB * TT];

__global__ void scores_kernel(const float* __restrict__ logits) {
    int idx = blockIdx.x * blockDim.x + threadIdx.x;
    if (idx < BB * TT) {
        float x = logits[idx];
        // sigmoid via fast exp + fast divide (MUFU EX2 + RCP)
        g_scores[idx] = __fdividef(1.0f, 1.0f + __expf(-x));
    }
}

// One block handles RPB consecutive rows of one batch.
// Row softmax WITHOUT max-subtraction: rel values are in (0,1), so exp(rel) is
// in (1,e) — numerically safe, and masked entries are exactly 0 (matching
// exp(-1e9 - max) == 0 in the reference's fp32 arithmetic).
__global__ __launch_bounds__(THREADS) void row_softmax_kernel(
    const int* __restrict__ seq_len,
    float* __restrict__ out)
{
    __shared__ float s_scores[TT];
    __shared__ float s_red[THREADS / 32];
    __shared__ float s_inv;

    const int b    = blockIdx.y;
    const int row0 = blockIdx.x * RPB;
    const int tid  = threadIdx.x;
    const int L    = seq_len[b];

    // stage this batch's scores into smem (coalesced float4)
    {
        const float4* src = reinterpret_cast<const float4*>(g_scores + b * TT);
        float4* dst = reinterpret_cast<float4*>(s_scores);
        #pragma unroll
        for (int k = 0; k < (TT / 4) / THREADS; k++)
            dst[tid + k * THREADS] = src[tid + k * THREADS];
    }
    __syncthreads();

    for (int r = 0; r < RPB; r++) {
        const int i = row0 + r;
        float* orow = out + ((size_t)b * TT + (size_t)i) * TT;

        if (i >= L) {
            // invalid row -> all zeros (uniform branch across block; no syncs inside)
            const float4 z = make_float4(0.f, 0.f, 0.f, 0.f);
            #pragma unroll
            for (int k = 0; k < (TT / 4) / THREADS; k++)
                reinterpret_cast<float4*>(orow)[tid + k * THREADS] = z;
            continue;
        }

        const float s_i = s_scores[i];
        float e[8];
        float psum = 0.f;

        // two float4 chunks: chunk c covers j in [c*1024, c*1024+1024)
        #pragma unroll
        for (int c = 0; c < 2; c++) {
            const int jbase = c * 1024 + tid * 4;
            const float4 sv = reinterpret_cast<const float4*>(s_scores)[c * THREADS + tid];
            const float sj[4] = {sv.x, sv.y, sv.z, sv.w};
            #pragma unroll
            for (int q = 0; q < 4; q++) {
                const int j = jbase + q;
                float ev = 0.f;
                if (j < L) {
                    const float x   = fmaf(-10.0f, fabsf(s_i - sj[q]), 5.0f);
                    const float sig = __fdividef(1.0f, 1.0f + __expf(-x));
                    ev = __expf(sig);
                }
                e[c * 4 + q] = ev;
                psum += ev;
            }
        }

        // block reduction of psum
        #pragma unroll
        for (int off = 16; off > 0; off >>= 1)
            psum += __shfl_xor_sync(0xFFFFFFFFu, psum, off);
        if ((tid & 31) == 0) s_red[tid >> 5] = psum;
        __syncthreads();
        if (tid == 0) {
            float tot = 0.f;
            #pragma unroll
            for (int w = 0; w < THREADS / 32; w++) tot += s_red[w];
            s_inv = __fdividef(1.0f, tot);
        }
        __syncthreads();
        const float inv = s_inv;

        // normalized store (float4, coalesced)
        #pragma unroll
        for (int c = 0; c < 2; c++) {
            const float4 v = make_float4(e[c * 4 + 0] * inv, e[c * 4 + 1] * inv,
                                         e[c * 4 + 2] * inv, e[c * 4 + 3] * inv);
            reinterpret_cast<float4*>(orow)[c * THREADS + tid] = v;
        }
        __syncthreads();   // protect s_red/s_inv before next row
    }
}

extern "C" void kernel_launch(void* const* d_in, const int* in_sizes, int n_in,
                              void* d_out, int out_size) {
    const float* logits  = (const float*)d_in[0];   // [16, 2048, 1] fp32
    const int*   seq_len = (const int*)d_in[1];     // [16] i32
    float*       out     = (float*)d_out;           // [16, 2048, 2048] fp32

    scores_kernel<<<(BB * TT + 255) / 256, 256>>>(logits);

    dim3 grid(TT / RPB, BB);
    row_softmax_kernel<<<grid, THREADS>>>(seq_len, out);
}

// round 3
// speedup vs baseline: 1.0801x; 1.0801x over previous
#include <cuda_runtime.h>
#include <cstdint>

// logits [16, 2048, 1] fp32, seq_len [16] i32, out [16, 2048, 2048] fp32.
#define BB 16
#define TT 2048
#define RPB 8          // rows per block
#define THREADS 256

// Fully fused: one kernel. Each block
//   1. computes sigmoid(logits[b,:]) for its batch into smem (8 KB, L2-fed),
//   2. runs a single-pass max-free softmax for RPB rows,
//   3. writes output with evict-streaming float4 stores.
//
// Max-free softmax is exact here: rel values are in (0.0067, 0.9933), so
// exp(rel) is in (1, e) — no overflow — and masked entries are exactly 0,
// matching exp(-1e9 - max) == 0 in the reference's fp32 arithmetic.
__global__ __launch_bounds__(THREADS) void fused_kernel(
    const float* __restrict__ logits,
    const int* __restrict__ seq_len,
    float* __restrict__ out)
{
    __shared__ float s_scores[TT];
    __shared__ float s_red[THREADS / 32];
    __shared__ float s_inv;

    const int b    = blockIdx.y;
    const int row0 = blockIdx.x * RPB;
    const int tid  = threadIdx.x;
    const int L    = seq_len[b];

    // compute this batch's scores into smem (coalesced float4 loads of logits)
    {
        const float4* src = reinterpret_cast<const float4*>(logits + b * TT);
        #pragma unroll
        for (int k = 0; k < (TT / 4) / THREADS; k++) {
            const float4 x = src[tid + k * THREADS];
            float4 s;
            s.x = __fdividef(1.0f, 1.0f + __expf(-x.x));
            s.y = __fdividef(1.0f, 1.0f + __expf(-x.y));
            s.z = __fdividef(1.0f, 1.0f + __expf(-x.z));
            s.w = __fdividef(1.0f, 1.0f + __expf(-x.w));
            reinterpret_cast<float4*>(s_scores)[tid + k * THREADS] = s;
        }
    }
    __syncthreads();

    for (int r = 0; r < RPB; r++) {
        const int i = row0 + r;
        float* orow = out + ((size_t)b * TT + (size_t)i) * TT;

        if (i >= L) {
            // invalid row -> all zeros (uniform branch; no syncs inside)
            const float4 z = make_float4(0.f, 0.f, 0.f, 0.f);
            #pragma unroll
            for (int k = 0; k < (TT / 4) / THREADS; k++)
                __stcs(reinterpret_cast<float4*>(orow) + tid + k * THREADS, z);
            continue;
        }

        const float s_i = s_scores[i];
        float e[8];
        float psum = 0.f;

        // chunk c covers j in [c*1024, c*1024+1024); this thread owns 4 j's.
        #pragma unroll
        for (int c = 0; c < 2; c++) {
            const int jbase = c * 1024 + tid * 4;
            const float4 sv = reinterpret_cast<const float4*>(s_scores)[c * THREADS + tid];
            const float sj[4] = {sv.x, sv.y, sv.z, sv.w};
            if (jbase + 3 < L) {
                // fully valid chunk: no per-element predication
                #pragma unroll
                for (int q = 0; q < 4; q++) {
                    const float x   = fmaf(-10.0f, fabsf(s_i - sj[q]), 5.0f);
                    const float sig = __fdividef(1.0f, 1.0f + __expf(-x));
                    const float ev  = __expf(sig);
                    e[c * 4 + q] = ev;
                    psum += ev;
                }
            } else {
                #pragma unroll
                for (int q = 0; q < 4; q++) {
                    const int j = jbase + q;
                    float ev = 0.f;
                    if (j < L) {
                        const float x   = fmaf(-10.0f, fabsf(s_i - sj[q]), 5.0f);
                        const float sig = __fdividef(1.0f, 1.0f + __expf(-x));
                        ev = __expf(sig);
                    }
                    e[c * 4 + q] = ev;
                    psum += ev;
                }
            }
        }

        // block reduction of psum
        #pragma unroll
        for (int off = 16; off > 0; off >>= 1)
            psum += __shfl_xor_sync(0xFFFFFFFFu, psum, off);
        if ((tid & 31) == 0) s_red[tid >> 5] = psum;
        __syncthreads();
        if (tid == 0) {
            float tot = 0.f;
            #pragma unroll
            for (int w = 0; w < THREADS / 32; w++) tot += s_red[w];
            s_inv = __fdividef(1.0f, tot);
        }
        __syncthreads();
        const float inv = s_inv;

        // normalized evict-streaming stores (float4, coalesced)
        #pragma unroll
        for (int c = 0; c < 2; c++) {
            const float4 v = make_float4(e[c * 4 + 0] * inv, e[c * 4 + 1] * inv,
                                         e[c * 4 + 2] * inv, e[c * 4 + 3] * inv);
            __stcs(reinterpret_cast<float4*>(orow) + c * THREADS + tid, v);
        }
        __syncthreads();   // protect s_red/s_inv before next row
    }
}

extern "C" void kernel_launch(void* const* d_in, const int* in_sizes, int n_in,
                              void* d_out, int out_size) {
    const float* logits  = (const float*)d_in[0];   // [16, 2048, 1] fp32
    const int*   seq_len = (const int*)d_in[1];     // [16] i32
    float*       out     = (float*)d_out;           // [16, 2048, 2048] fp32

    dim3 grid(TT / RPB, BB);
    fused_kernel<<<grid, THREADS>>>(logits, seq_len, out);
}